// round 13
// baseline (speedup 1.0000x reference)
#include <cuda_runtime.h>
#include <cuda_fp16.h>
#include <cstdint>
#include <math.h>

#define BSQ 8192   // B*S tokens
#define HID 1024
#define DFF 4096
#define NE  8
#define NK  2048

// GEMM tiling: CTA 128x128x64, 4 warps of 64x64, fp16 m16n8k16, 2 CTAs/SM
#define BM 128
#define BN 128
#define BK 64
#define NSTAGE 3
#define GTHREADS 128
#define RSA 72                           // A row stride (halves): 144B rows, ldsm conflict-free
#define RSB 136                          // B row stride (halves): 272B rows, conflict-free
#define A_BYTES_ST (BM * RSA * 2)        // 18432
#define B_BYTES_ST (BK * RSB * 2)        // 17408
#define STAGE_BYTES (A_BYTES_ST + B_BYTES_ST)   // 35840
#define SMEM_SZ (NSTAGE * STAGE_BYTES)          // 107520 -> 2 CTAs/SM

#define N4 ((size_t)NE * HID * DFF / 4)  // float4 count per weight tensor

// ---------------- scratch -------------------------------------------------
__device__ float g_scores[BSQ * NE];
__device__ int   g_idx[NE * NK];
__device__ float g_gate[NE * NK];
__device__ __align__(256) __half g_h1h[(size_t)NE * NK * DFF];   // 128MB h1 (fp16)
__device__ __align__(256) __half g_Ah[(size_t)NE * NK * HID];    // 32MB gathered tokens
__device__ __align__(256) __half g_w1h[(size_t)NE * HID * DFF];  // 64MB w1 fp16
__device__ __align__(256) __half g_w2h[(size_t)NE * DFF * HID];  // 64MB w2 fp16

// ---------------- helpers ---------------------------------------------------
__device__ __forceinline__ uint32_t smem_u32(const void* p) {
    uint32_t a;
    asm("{ .reg .u64 t; cvta.to.shared.u64 t, %1; cvt.u32.u64 %0, t; }" : "=r"(a) : "l"(p));
    return a;
}
__device__ __forceinline__ void cp16(uint32_t dst, const void* src) {
    asm volatile("cp.async.cg.shared.global [%0], [%1], 16;" :: "r"(dst), "l"(src));
}
__device__ __forceinline__ void cp_commit() {
    asm volatile("cp.async.commit_group;" ::: "memory");
}
__device__ __forceinline__ void cp_wait1() {
    asm volatile("cp.async.wait_group 1;" ::: "memory");
}
__device__ __forceinline__ void ldsm4(uint32_t* r, uint32_t addr) {
    asm volatile("ldmatrix.sync.aligned.m8n8.x4.shared.b16 {%0,%1,%2,%3}, [%4];"
                 : "=r"(r[0]), "=r"(r[1]), "=r"(r[2]), "=r"(r[3]) : "r"(addr));
}
__device__ __forceinline__ void ldsm4t(uint32_t* r, uint32_t addr) {
    asm volatile("ldmatrix.sync.aligned.m8n8.x4.trans.shared.b16 {%0,%1,%2,%3}, [%4];"
                 : "=r"(r[0]), "=r"(r[1]), "=r"(r[2]), "=r"(r[3]) : "r"(addr));
}
__device__ __forceinline__ void mma_f16(float* d, const uint32_t* a, const uint32_t* b) {
    asm volatile("mma.sync.aligned.m16n8k16.row.col.f32.f16.f16.f32 "
                 "{%0,%1,%2,%3}, {%4,%5,%6,%7}, {%8,%9}, {%0,%1,%2,%3};"
                 : "+f"(d[0]), "+f"(d[1]), "+f"(d[2]), "+f"(d[3])
                 : "r"(a[0]), "r"(a[1]), "r"(a[2]), "r"(a[3]), "r"(b[0]), "r"(b[1]));
}

// grid-stride fp32->fp16 weight conversion (both tensors) over float4 [lo, hi)
__device__ __forceinline__ void cvt_chunk(const float* __restrict__ w1,
                                          const float* __restrict__ w2,
                                          size_t lo, size_t hi,
                                          int cb, int ncb) {
    const size_t stride = (size_t)ncb * blockDim.x;
    for (size_t i = lo + (size_t)cb * blockDim.x + threadIdx.x; i < hi; i += stride) {
        float4 a = ((const float4*)w1)[i];
        ((__half2*)g_w1h)[2 * i]     = __floats2half2_rn(a.x, a.y);
        ((__half2*)g_w1h)[2 * i + 1] = __floats2half2_rn(a.z, a.w);
        float4 b = ((const float4*)w2)[i];
        ((__half2*)g_w2h)[2 * i]     = __floats2half2_rn(b.x, b.y);
        ((__half2*)g_w2h)[2 * i + 1] = __floats2half2_rn(b.z, b.w);
    }
}

// ---------------- phase 1: router + cvt chunk 1 -----------------------------
__global__ void router_cvt(const float* __restrict__ x,
                           const float* __restrict__ rw,
                           const float* __restrict__ rb,
                           const float* __restrict__ w1,
                           const float* __restrict__ w2) {
    __shared__ float srw[NE][HID];
    __shared__ float srb[NE];
    if (blockIdx.x >= BSQ / 8) {
        cvt_chunk(w1, w2, 0, N4 / 3, blockIdx.x - BSQ / 8, gridDim.x - BSQ / 8);
        return;
    }
    const int tid = threadIdx.x;
    for (int i = tid; i < HID * NE; i += 256) {
        int h = i >> 3, e = i & 7;
        srw[e][h] = rw[i];
    }
    if (tid < NE) srb[tid] = rb[tid];
    __syncthreads();

    const int w = tid >> 5, lane = tid & 31;
    const int t = blockIdx.x * 8 + w;
    const float* xr = x + (size_t)t * HID;
    float acc[NE];
#pragma unroll
    for (int e = 0; e < NE; e++) acc[e] = 0.f;
    for (int h = lane; h < HID; h += 32) {
        float xv = xr[h];
#pragma unroll
        for (int e = 0; e < NE; e++) acc[e] = fmaf(xv, srw[e][h], acc[e]);
    }
#pragma unroll
    for (int e = 0; e < NE; e++) {
#pragma unroll
        for (int off = 16; off > 0; off >>= 1)
            acc[e] += __shfl_down_sync(0xffffffffu, acc[e], off);
    }
    if (lane == 0) {
        float m = -1e30f;
#pragma unroll
        for (int e = 0; e < NE; e++) { acc[e] += srb[e]; m = fmaxf(m, acc[e]); }
        float s = 0.f;
#pragma unroll
        for (int e = 0; e < NE; e++) { acc[e] = expf(acc[e] - m); s += acc[e]; }
        float inv = 1.f / s;
#pragma unroll
        for (int e = 0; e < NE; e++) g_scores[(size_t)t * NE + e] = acc[e] * inv;
    }
}

// ---------------- phase 2: top-K + cvt chunk 2 ------------------------------
__global__ void topk_cvt(const float* __restrict__ w1, const float* __restrict__ w2) {
    __shared__ int sg[1024];
    __shared__ int se[1024];
    __shared__ int red;
    if (blockIdx.x >= NE) {
        cvt_chunk(w1, w2, N4 / 3, (2 * N4) / 3, blockIdx.x - NE, gridDim.x - NE);
        return;
    }
    const int e = blockIdx.x;
    const int tid = threadIdx.x;

    unsigned v[8];
#pragma unroll
    for (int j = 0; j < 8; j++) {
        int i = tid * 8 + j;
        v[j] = __float_as_uint(g_scores[(size_t)i * NE + e]);
    }
    if (tid == 0) red = 0;
    __syncthreads();

    // softmax scores in [0,2) -> bits 31,30 always 0; radix from bit 29
    unsigned prefix = 0;
    int kr = NK;
    for (int bit = 29; bit >= 0; --bit) {
        unsigned want = (prefix >> bit) | 1u;
        int local = 0;
#pragma unroll
        for (int j = 0; j < 8; j++) local += ((v[j] >> bit) == want);
#pragma unroll
        for (int off = 16; off > 0; off >>= 1)
            local += __shfl_down_sync(0xffffffffu, local, off);
        if ((tid & 31) == 0) atomicAdd(&red, local);
        __syncthreads();
        int cnt = red;
        __syncthreads();
        if (tid == 0) red = 0;
        if (cnt >= kr) prefix |= (1u << bit); else kr -= cnt;
        __syncthreads();
    }
    const unsigned thr = prefix;

    int cg = 0, ce = 0;
#pragma unroll
    for (int j = 0; j < 8; j++) { cg += (v[j] > thr); ce += (v[j] == thr); }
    sg[tid] = cg; se[tid] = ce;
    __syncthreads();
    for (int d = 1; d < 1024; d <<= 1) {
        int a = (tid >= d) ? sg[tid - d] : 0;
        int b = (tid >= d) ? se[tid - d] : 0;
        __syncthreads();
        sg[tid] += a; se[tid] += b;
        __syncthreads();
    }
    const int C = sg[1023];
    int pg = sg[tid] - cg;
    int pe = se[tid] - ce;
    const int need = NK - C;
#pragma unroll
    for (int j = 0; j < 8; j++) {
        int tok = tid * 8 + j;
        if (v[j] > thr) {
            g_idx[e * NK + pg] = tok;
            g_gate[e * NK + pg] = __uint_as_float(v[j]);
            pg++;
        } else if (v[j] == thr) {
            if (pe < need) {
                int pos = C + pe;
                g_idx[e * NK + pos] = tok;
                g_gate[e * NK + pos] = __uint_as_float(v[j]);
            }
            pe++;
        }
    }
}

// ---------------- phase 3: gather + cvt chunk 3 -----------------------------
__global__ void gather_cvt(const float* __restrict__ x,
                           const float* __restrict__ w1,
                           const float* __restrict__ w2) {
    if (blockIdx.x >= NE * NK) {
        cvt_chunk(w1, w2, (2 * N4) / 3, N4, blockIdx.x - NE * NK, gridDim.x - NE * NK);
        return;
    }
    const int row = blockIdx.x;
    const int tok = g_idx[row];
    const float4* s = (const float4*)(x + (size_t)tok * HID);
    float4 v = s[threadIdx.x];
    __half2* d = (__half2*)(g_Ah + (size_t)row * HID) + threadIdx.x * 2;
    d[0] = __floats2half2_rn(v.x, v.y);
    d[1] = __floats2half2_rn(v.z, v.w);
}

// ---------------- fp16 mma mainloop (4 warps, 64x64 warp tiles) -------------
__device__ __forceinline__ void load_stage(uint32_t sb, int buf, int tid,
                                           const __half* aG, int K,
                                           const __half* bG, int Nld, int k0) {
    const uint32_t baseA = sb + buf * STAGE_BYTES;
    const uint32_t baseB = baseA + A_BYTES_ST;
#pragma unroll
    for (int i = 0; i < 8; i++) {                       // A: 1024 cp16 (128 rows x 128B)
        int id = tid + (i << 7);
        int r = id >> 3, c = id & 7;
        cp16(baseA + r * (RSA * 2) + c * 16, aG + (size_t)r * K + k0 + c * 8);
    }
#pragma unroll
    for (int i = 0; i < 8; i++) {                       // B: 1024 cp16 (64 rows x 256B)
        int id = tid + (i << 7);
        int kr = id >> 4, nc = id & 15;
        cp16(baseB + kr * (RSB * 2) + nc * 16, bG + (size_t)(k0 + kr) * Nld + nc * 8);
    }
}

__device__ __forceinline__ void gemm_mainloop(float acc[4][8][4], uint32_t sb, int tid,
                                              const __half* aG,
                                              const __half* bG, int Nld, int K) {
    const int wid = tid >> 5, lane = tid & 31;
    const int wm = wid & 1, wn = wid >> 1;              // 2 x 2 warp grid, 64x64 tiles
    const int lane15 = lane & 15, laneh = lane >> 4;
    const int KT = K / BK;
    const uint32_t aLane = (uint32_t)(wm * 64 + lane15) * (RSA * 2) + laneh * 16;
    const uint32_t bLane = (uint32_t)lane15 * (RSB * 2) + wn * 128 + laneh * 16;

#pragma unroll
    for (int mt = 0; mt < 4; mt++)
#pragma unroll
        for (int nt = 0; nt < 8; nt++)
#pragma unroll
            for (int q = 0; q < 4; q++) acc[mt][nt][q] = 0.f;

    for (int s = 0; s < NSTAGE - 1; s++) {
        load_stage(sb, s, tid, aG, K, bG, Nld, s * BK);
        cp_commit();
    }

    for (int k = 0; k < KT; k++) {
        const int buf = k % NSTAGE;
        cp_wait1();
        __syncthreads();   // single barrier per iter: also fences prior-iter reads
                           // before this iter's loads overwrite buf (k+2)%3

        const uint32_t bufA = sb + buf * STAGE_BYTES + aLane;
        const uint32_t bufB = sb + buf * STAGE_BYTES + A_BYTES_ST + bLane;
#pragma unroll
        for (int kk = 0; kk < 4; kk++) {
            uint32_t aF[4][4], bF[4][4];
#pragma unroll
            for (int mt = 0; mt < 4; mt++)
                ldsm4(aF[mt], bufA + mt * (16 * RSA * 2) + kk * 32);
#pragma unroll
            for (int np = 0; np < 4; np++)
                ldsm4t(bF[np], bufB + kk * (16 * RSB * 2) + np * 32);
#pragma unroll
            for (int mt = 0; mt < 4; mt++)
#pragma unroll
                for (int np = 0; np < 4; np++) {
                    mma_f16(acc[mt][2 * np],     aF[mt], &bF[np][0]);
                    mma_f16(acc[mt][2 * np + 1], aF[mt], &bF[np][2]);
                }
        }

        const int pf = k + NSTAGE - 1;
        if (pf < KT) load_stage(sb, pf % NSTAGE, tid, aG, K, bG, Nld, pf * BK);
        cp_commit();   // empty group when no prefetch keeps wait_group invariant
    }
}

// ---------------- GEMM1: g_h1h = half(relu(g_Ah @ w1h + b1)) ----------------
__global__ __launch_bounds__(GTHREADS, 2)
void gemm1_tc(const float* __restrict__ b1) {
    extern __shared__ char smem[];
    const uint32_t sb = smem_u32(smem);
    const int tid = threadIdx.x;
    const int e = blockIdx.z, n0 = blockIdx.x * BN, m0 = blockIdx.y * BM;

    const __half* aG = g_Ah + (size_t)(e * NK + m0) * HID;
    const __half* bG = g_w1h + (size_t)e * HID * DFF + n0;
    float acc[4][8][4];
    gemm_mainloop(acc, sb, tid, aG, bG, DFF, HID);

    const int wid = tid >> 5, lane = tid & 31;
    const int wm = wid & 1, wn = wid >> 1;
    const int g = lane >> 2, c = lane & 3;
#pragma unroll
    for (int mt = 0; mt < 4; mt++) {
        const int r0 = m0 + wm * 64 + mt * 16 + g;
#pragma unroll
        for (int nt = 0; nt < 8; nt++) {
            const int cc = n0 + wn * 64 + nt * 8 + 2 * c;
            const float bx = b1[(size_t)e * DFF + cc];
            const float by = b1[(size_t)e * DFF + cc + 1];
            __half2 v0 = __floats2half2_rn(fmaxf(acc[mt][nt][0] + bx, 0.f),
                                           fmaxf(acc[mt][nt][1] + by, 0.f));
            __half2 v1 = __floats2half2_rn(fmaxf(acc[mt][nt][2] + bx, 0.f),
                                           fmaxf(acc[mt][nt][3] + by, 0.f));
            *(__half2*)&g_h1h[(size_t)(e * NK + r0) * DFF + cc] = v0;
            *(__half2*)&g_h1h[(size_t)(e * NK + r0 + 8) * DFF + cc] = v1;
        }
    }
}

// ---------------- GEMM2: out += gate * (g_h1h @ w2h + b2) -------------------
__global__ __launch_bounds__(GTHREADS, 2)
void gemm2_tc(const float* __restrict__ b2, float* __restrict__ out) {
    extern __shared__ char smem[];
    const uint32_t sb = smem_u32(smem);
    const int tid = threadIdx.x;
    const int e = blockIdx.z, n0 = blockIdx.x * BN, m0 = blockIdx.y * BM;

    const __half* aG = g_h1h + (size_t)(e * NK + m0) * DFF;
    const __half* bG = g_w2h + (size_t)e * DFF * HID + n0;
    float acc[4][8][4];
    gemm_mainloop(acc, sb, tid, aG, bG, HID, DFF);

    const int wid = tid >> 5, lane = tid & 31;
    const int wm = wid & 1, wn = wid >> 1;
    const int g = lane >> 2, c = lane & 3;
#pragma unroll
    for (int mt = 0; mt < 4; mt++) {
        const int r0 = m0 + wm * 64 + mt * 16 + g;
        const int tok0 = g_idx[e * NK + r0];
        const int tok1 = g_idx[e * NK + r0 + 8];
        const float g0 = g_gate[e * NK + r0];
        const float g1 = g_gate[e * NK + r0 + 8];
#pragma unroll
        for (int nt = 0; nt < 8; nt++) {
            const int cc = n0 + wn * 64 + nt * 8 + 2 * c;
            const float bx = b2[(size_t)e * HID + cc];
            const float by = b2[(size_t)e * HID + cc + 1];
            atomicAdd(out + (size_t)tok0 * HID + cc,     (acc[mt][nt][0] + bx) * g0);
            atomicAdd(out + (size_t)tok0 * HID + cc + 1, (acc[mt][nt][1] + by) * g0);
            atomicAdd(out + (size_t)tok1 * HID + cc,     (acc[mt][nt][2] + bx) * g1);
            atomicAdd(out + (size_t)tok1 * HID + cc + 1, (acc[mt][nt][3] + by) * g1);
        }
    }
}

// ---------------- launch ----------------------------------------------------
extern "C" void kernel_launch(void* const* d_in, const int* in_sizes, int n_in,
                              void* d_out, int out_size) {
    const float* x  = (const float*)d_in[0];
    const float* rw = (const float*)d_in[1];
    const float* rb = (const float*)d_in[2];
    const float* w1 = (const float*)d_in[3];
    const float* b1 = (const float*)d_in[4];
    const float* w2 = (const float*)d_in[5];
    const float* b2 = (const float*)d_in[6];
    float* out = (float*)d_out;

    cudaFuncSetAttribute(gemm1_tc, cudaFuncAttributeMaxDynamicSharedMemorySize, SMEM_SZ);
    cudaFuncSetAttribute(gemm2_tc, cudaFuncAttributeMaxDynamicSharedMemorySize, SMEM_SZ);

    cudaMemsetAsync(d_out, 0, (size_t)out_size * sizeof(float), 0);
    router_cvt<<<BSQ / 8 + 2048, 256>>>(x, rw, rb, w1, w2);
    topk_cvt<<<NE + 504, 1024>>>(w1, w2);
    gather_cvt<<<NE * NK + 2048, 256>>>(x, w1, w2);
    gemm1_tc<<<dim3(DFF / BN, NK / BM, NE), GTHREADS, SMEM_SZ>>>(b1);
    gemm2_tc<<<dim3(HID / BN, NK / BM, NE), GTHREADS, SMEM_SZ>>>(b2, out);
}

// round 14
// speedup vs baseline: 1.0300x; 1.0300x over previous
#include <cuda_runtime.h>
#include <cuda_fp16.h>
#include <cstdint>
#include <math.h>

#define BSQ 8192   // B*S tokens
#define HID 1024
#define DFF 4096
#define NE  8
#define NK  2048

// GEMM tiling: CTA 128x128x64, 8 warps of 64x32, fp16 m16n8k16, 2 CTAs/SM (R10 config)
#define BM 128
#define BN 128
#define BK 64
#define NSTAGE 3
#define RSA 72                           // A row stride (halves): 144B rows, ldsm conflict-free
#define RSB 136                          // B row stride (halves): 272B rows, conflict-free
#define A_BYTES_ST (BM * RSA * 2)        // 18432
#define B_BYTES_ST (BK * RSB * 2)        // 17408
#define STAGE_BYTES (A_BYTES_ST + B_BYTES_ST)   // 35840
#define SMEM_SZ (NSTAGE * STAGE_BYTES)          // 107520 -> 2 CTAs/SM

#define N4 ((size_t)NE * HID * DFF / 4)  // float4 count per weight tensor
#define OUT4 ((size_t)BSQ * HID / 4)     // float4 count of output
#define C1 ((N4 * 8) / 25)               // cvt chunk boundaries (0.32 / 0.72)
#define C2 ((N4 * 18) / 25)

// ---------------- scratch -------------------------------------------------
__device__ float g_scores[BSQ * NE];
__device__ int   g_idx[NE * NK];
__device__ float g_gate[NE * NK];
__device__ __align__(256) __half g_h1h[(size_t)NE * NK * DFF];   // 128MB h1 (fp16)
__device__ __align__(256) __half g_Ah[(size_t)NE * NK * HID];    // 32MB gathered tokens
__device__ __align__(256) __half g_w1h[(size_t)NE * HID * DFF];  // 64MB w1 fp16
__device__ __align__(256) __half g_w2h[(size_t)NE * DFF * HID];  // 64MB w2 fp16

// ---------------- helpers ---------------------------------------------------
__device__ __forceinline__ uint32_t smem_u32(const void* p) {
    uint32_t a;
    asm("{ .reg .u64 t; cvta.to.shared.u64 t, %1; cvt.u32.u64 %0, t; }" : "=r"(a) : "l"(p));
    return a;
}
__device__ __forceinline__ void cp16(uint32_t dst, const void* src) {
    asm volatile("cp.async.cg.shared.global [%0], [%1], 16;" :: "r"(dst), "l"(src));
}
__device__ __forceinline__ void cp_commit() {
    asm volatile("cp.async.commit_group;" ::: "memory");
}
__device__ __forceinline__ void cp_wait1() {
    asm volatile("cp.async.wait_group 1;" ::: "memory");
}
__device__ __forceinline__ void ldsm4(uint32_t* r, uint32_t addr) {
    asm volatile("ldmatrix.sync.aligned.m8n8.x4.shared.b16 {%0,%1,%2,%3}, [%4];"
                 : "=r"(r[0]), "=r"(r[1]), "=r"(r[2]), "=r"(r[3]) : "r"(addr));
}
__device__ __forceinline__ void ldsm4t(uint32_t* r, uint32_t addr) {
    asm volatile("ldmatrix.sync.aligned.m8n8.x4.trans.shared.b16 {%0,%1,%2,%3}, [%4];"
                 : "=r"(r[0]), "=r"(r[1]), "=r"(r[2]), "=r"(r[3]) : "r"(addr));
}
__device__ __forceinline__ void mma_f16(float* d, const uint32_t* a, const uint32_t* b) {
    asm volatile("mma.sync.aligned.m16n8k16.row.col.f32.f16.f16.f32 "
                 "{%0,%1,%2,%3}, {%4,%5,%6,%7}, {%8,%9}, {%0,%1,%2,%3};"
                 : "+f"(d[0]), "+f"(d[1]), "+f"(d[2]), "+f"(d[3])
                 : "r"(a[0]), "r"(a[1]), "r"(a[2]), "r"(a[3]), "r"(b[0]), "r"(b[1]));
}

// grid-stride fp32->fp16 weight conversion (both tensors) over float4 [lo, hi)
// unrolled x2: 4 independent 16B loads in flight per iteration (MLP >= 4)
__device__ __forceinline__ void cvt_chunk(const float* __restrict__ w1,
                                          const float* __restrict__ w2,
                                          size_t lo, size_t hi,
                                          int cb, int ncb) {
    const size_t stride = (size_t)ncb * blockDim.x;
    size_t i = lo + (size_t)cb * blockDim.x + threadIdx.x;
    for (; i + stride < hi; i += 2 * stride) {
        const size_t j = i + stride;
        float4 a0 = ((const float4*)w1)[i];
        float4 b0 = ((const float4*)w2)[i];
        float4 a1 = ((const float4*)w1)[j];
        float4 b1 = ((const float4*)w2)[j];
        ((__half2*)g_w1h)[2 * i]     = __floats2half2_rn(a0.x, a0.y);
        ((__half2*)g_w1h)[2 * i + 1] = __floats2half2_rn(a0.z, a0.w);
        ((__half2*)g_w2h)[2 * i]     = __floats2half2_rn(b0.x, b0.y);
        ((__half2*)g_w2h)[2 * i + 1] = __floats2half2_rn(b0.z, b0.w);
        ((__half2*)g_w1h)[2 * j]     = __floats2half2_rn(a1.x, a1.y);
        ((__half2*)g_w1h)[2 * j + 1] = __floats2half2_rn(a1.z, a1.w);
        ((__half2*)g_w2h)[2 * j]     = __floats2half2_rn(b1.x, b1.y);
        ((__half2*)g_w2h)[2 * j + 1] = __floats2half2_rn(b1.z, b1.w);
    }
    if (i < hi) {
        float4 a0 = ((const float4*)w1)[i];
        float4 b0 = ((const float4*)w2)[i];
        ((__half2*)g_w1h)[2 * i]     = __floats2half2_rn(a0.x, a0.y);
        ((__half2*)g_w1h)[2 * i + 1] = __floats2half2_rn(a0.z, a0.w);
        ((__half2*)g_w2h)[2 * i]     = __floats2half2_rn(b0.x, b0.y);
        ((__half2*)g_w2h)[2 * i + 1] = __floats2half2_rn(b0.z, b0.w);
    }
}

// ---------------- phase 1: router + cvt chunk 1 + out zeroing ---------------
#define RCV_CVT 1536
#define RCV_ZERO 512
__global__ void router_cvt(const float* __restrict__ x,
                           const float* __restrict__ rw,
                           const float* __restrict__ rb,
                           const float* __restrict__ w1,
                           const float* __restrict__ w2,
                           float* __restrict__ out) {
    __shared__ float srw[NE][HID];
    __shared__ float srb[NE];
    if (blockIdx.x >= BSQ / 8 + RCV_CVT) {             // zero the output
        const int cb = blockIdx.x - BSQ / 8 - RCV_CVT;
        const size_t stride = (size_t)RCV_ZERO * blockDim.x;
        const float4 z = make_float4(0.f, 0.f, 0.f, 0.f);
        for (size_t i = (size_t)cb * blockDim.x + threadIdx.x; i < OUT4; i += stride)
            ((float4*)out)[i] = z;
        return;
    }
    if (blockIdx.x >= BSQ / 8) {
        cvt_chunk(w1, w2, 0, C1, blockIdx.x - BSQ / 8, RCV_CVT);
        return;
    }
    const int tid = threadIdx.x;
    for (int i = tid; i < HID * NE; i += 256) {
        int h = i >> 3, e = i & 7;
        srw[e][h] = rw[i];
    }
    if (tid < NE) srb[tid] = rb[tid];
    __syncthreads();

    const int w = tid >> 5, lane = tid & 31;
    const int t = blockIdx.x * 8 + w;
    const float* xr = x + (size_t)t * HID;
    float acc[NE];
#pragma unroll
    for (int e = 0; e < NE; e++) acc[e] = 0.f;
    for (int h = lane; h < HID; h += 32) {
        float xv = xr[h];
#pragma unroll
        for (int e = 0; e < NE; e++) acc[e] = fmaf(xv, srw[e][h], acc[e]);
    }
#pragma unroll
    for (int e = 0; e < NE; e++) {
#pragma unroll
        for (int off = 16; off > 0; off >>= 1)
            acc[e] += __shfl_down_sync(0xffffffffu, acc[e], off);
    }
    if (lane == 0) {
        float m = -1e30f;
#pragma unroll
        for (int e = 0; e < NE; e++) { acc[e] += srb[e]; m = fmaxf(m, acc[e]); }
        float s = 0.f;
#pragma unroll
        for (int e = 0; e < NE; e++) { acc[e] = expf(acc[e] - m); s += acc[e]; }
        float inv = 1.f / s;
#pragma unroll
        for (int e = 0; e < NE; e++) g_scores[(size_t)t * NE + e] = acc[e] * inv;
    }
}

// ---------------- phase 2: top-K + cvt chunk 2 ------------------------------
__global__ void topk_cvt(const float* __restrict__ w1, const float* __restrict__ w2) {
    __shared__ int sg[1024];
    __shared__ int se[1024];
    __shared__ int red;
    if (blockIdx.x >= NE) {
        cvt_chunk(w1, w2, C1, C2, blockIdx.x - NE, gridDim.x - NE);
        return;
    }
    const int e = blockIdx.x;
    const int tid = threadIdx.x;

    unsigned v[8];
#pragma unroll
    for (int j = 0; j < 8; j++) {
        int i = tid * 8 + j;
        v[j] = __float_as_uint(g_scores[(size_t)i * NE + e]);
    }
    if (tid == 0) red = 0;
    __syncthreads();

    // softmax scores in [0,2) -> bits 31,30 always 0; radix from bit 29
    unsigned prefix = 0;
    int kr = NK;
    for (int bit = 29; bit >= 0; --bit) {
        unsigned want = (prefix >> bit) | 1u;
        int local = 0;
#pragma unroll
        for (int j = 0; j < 8; j++) local += ((v[j] >> bit) == want);
#pragma unroll
        for (int off = 16; off > 0; off >>= 1)
            local += __shfl_down_sync(0xffffffffu, local, off);
        if ((tid & 31) == 0) atomicAdd(&red, local);
        __syncthreads();
        int cnt = red;
        __syncthreads();
        if (tid == 0) red = 0;
        if (cnt >= kr) prefix |= (1u << bit); else kr -= cnt;
        __syncthreads();
    }
    const unsigned thr = prefix;

    int cg = 0, ce = 0;
#pragma unroll
    for (int j = 0; j < 8; j++) { cg += (v[j] > thr); ce += (v[j] == thr); }
    sg[tid] = cg; se[tid] = ce;
    __syncthreads();
    for (int d = 1; d < 1024; d <<= 1) {
        int a = (tid >= d) ? sg[tid - d] : 0;
        int b = (tid >= d) ? se[tid - d] : 0;
        __syncthreads();
        sg[tid] += a; se[tid] += b;
        __syncthreads();
    }
    const int C = sg[1023];
    int pg = sg[tid] - cg;
    int pe = se[tid] - ce;
    const int need = NK - C;
#pragma unroll
    for (int j = 0; j < 8; j++) {
        int tok = tid * 8 + j;
        if (v[j] > thr) {
            g_idx[e * NK + pg] = tok;
            g_gate[e * NK + pg] = __uint_as_float(v[j]);
            pg++;
        } else if (v[j] == thr) {
            if (pe < need) {
                int pos = C + pe;
                g_idx[e * NK + pos] = tok;
                g_gate[e * NK + pos] = __uint_as_float(v[j]);
            }
            pe++;
        }
    }
}

// ---------------- phase 3: gather + cvt chunk 3 -----------------------------
__global__ void gather_cvt(const float* __restrict__ x,
                           const float* __restrict__ w1,
                           const float* __restrict__ w2) {
    if (blockIdx.x >= NE * NK) {
        cvt_chunk(w1, w2, C2, N4, blockIdx.x - NE * NK, gridDim.x - NE * NK);
        return;
    }
    const int row = blockIdx.x;
    const int tok = g_idx[row];
    const float4* s = (const float4*)(x + (size_t)tok * HID);
    float4 v = s[threadIdx.x];
    __half2* d = (__half2*)(g_Ah + (size_t)row * HID) + threadIdx.x * 2;
    d[0] = __floats2half2_rn(v.x, v.y);
    d[1] = __floats2half2_rn(v.z, v.w);
}

// ---------------- fp16 mma mainloop (R10 config: 8 warps, 64x32 tiles) ------
// A rows at aG with row stride Ast (halves); depth Kd; B rows [k][Nld] at bG.
__device__ __forceinline__ void load_stage(uint32_t sb, int buf, int tid,
                                           const __half* aG, int Ast,
                                           const __half* bG, int Nld, int k0) {
    const uint32_t baseA = sb + buf * STAGE_BYTES;
    const uint32_t baseB = baseA + A_BYTES_ST;
#pragma unroll
    for (int i = 0; i < 4; i++) {                       // A: 1024 cp16 (128 rows x 128B)
        int id = tid + (i << 8);
        int r = id >> 3, c = id & 7;
        cp16(baseA + r * (RSA * 2) + c * 16, aG + (size_t)r * Ast + k0 + c * 8);
    }
#pragma unroll
    for (int i = 0; i < 4; i++) {                       // B: 1024 cp16 (64 rows x 256B)
        int id = tid + (i << 8);
        int kr = id >> 4, nc = id & 15;
        cp16(baseB + kr * (RSB * 2) + nc * 16, bG + (size_t)(k0 + kr) * Nld + nc * 8);
    }
}

__device__ __forceinline__ void gemm_mainloop(float acc[4][4][4], uint32_t sb, int tid,
                                              const __half* aG, int Ast,
                                              const __half* bG, int Nld, int Kd) {
    const int wid = tid >> 5, lane = tid & 31;
    const int wm = wid & 1, wn = wid >> 1;              // 2 x 4 warp grid, 64x32 tiles
    const int lane15 = lane & 15, laneh = lane >> 4;
    const int KT = Kd / BK;
    const uint32_t aLane = (uint32_t)(wm * 64 + lane15) * (RSA * 2) + laneh * 16;
    const uint32_t bLane = (uint32_t)lane15 * (RSB * 2) + wn * 64 + laneh * 16;

#pragma unroll
    for (int mt = 0; mt < 4; mt++)
#pragma unroll
        for (int nt = 0; nt < 4; nt++)
#pragma unroll
            for (int q = 0; q < 4; q++) acc[mt][nt][q] = 0.f;

    for (int s = 0; s < NSTAGE - 1; s++) {
        load_stage(sb, s, tid, aG, Ast, bG, Nld, s * BK);
        cp_commit();
    }

    for (int k = 0; k < KT; k++) {
        const int buf = k % NSTAGE;
        cp_wait1();
        __syncthreads();   // single barrier per iter: also fences prior-iter reads
                           // before this iter's loads overwrite buf (k+2)%3

        const uint32_t bufA = sb + buf * STAGE_BYTES + aLane;
        const uint32_t bufB = sb + buf * STAGE_BYTES + A_BYTES_ST + bLane;
#pragma unroll
        for (int kk = 0; kk < 4; kk++) {
            uint32_t aF[4][4], bF[2][4];
#pragma unroll
            for (int mt = 0; mt < 4; mt++)
                ldsm4(aF[mt], bufA + mt * (16 * RSA * 2) + kk * 32);
#pragma unroll
            for (int np = 0; np < 2; np++)
                ldsm4t(bF[np], bufB + kk * (16 * RSB * 2) + np * 32);
#pragma unroll
            for (int mt = 0; mt < 4; mt++)
#pragma unroll
                for (int np = 0; np < 2; np++) {
                    mma_f16(acc[mt][2 * np],     aF[mt], &bF[np][0]);
                    mma_f16(acc[mt][2 * np + 1], aF[mt], &bF[np][2]);
                }
        }

        const int pf = k + NSTAGE - 1;
        if (pf < KT) load_stage(sb, pf % NSTAGE, tid, aG, Ast, bG, Nld, pf * BK);
        cp_commit();   // empty group when no prefetch keeps wait_group invariant
    }
}

// ---------------- GEMM1: g_h1h = half(relu(g_Ah @ w1h + b1)) ----------------
__global__ __launch_bounds__(256, 2)
void gemm1_tc(const float* __restrict__ b1) {
    extern __shared__ char smem[];
    const uint32_t sb = smem_u32(smem);
    const int tid = threadIdx.x;
    const int e = blockIdx.z, n0 = blockIdx.x * BN, m0 = blockIdx.y * BM;

    const __half* aG = g_Ah + (size_t)(e * NK + m0) * HID;
    const __half* bG = g_w1h + (size_t)e * HID * DFF + n0;
    float acc[4][4][4];
    gemm_mainloop(acc, sb, tid, aG, HID, bG, DFF, HID);

    const int wid = tid >> 5, lane = tid & 31;
    const int wm = wid & 1, wn = wid >> 1;
    const int g = lane >> 2, c = lane & 3;
#pragma unroll
    for (int mt = 0; mt < 4; mt++) {
        const int r0 = m0 + wm * 64 + mt * 16 + g;
#pragma unroll
        for (int nt = 0; nt < 4; nt++) {
            const int cc = n0 + wn * 32 + nt * 8 + 2 * c;
            const float bx = b1[(size_t)e * DFF + cc];
            const float by = b1[(size_t)e * DFF + cc + 1];
            __half2 v0 = __floats2half2_rn(fmaxf(acc[mt][nt][0] + bx, 0.f),
                                           fmaxf(acc[mt][nt][1] + by, 0.f));
            __half2 v1 = __floats2half2_rn(fmaxf(acc[mt][nt][2] + bx, 0.f),
                                           fmaxf(acc[mt][nt][3] + by, 0.f));
            *(__half2*)&g_h1h[(size_t)(e * NK + r0) * DFF + cc] = v0;
            *(__half2*)&g_h1h[(size_t)(e * NK + r0 + 8) * DFF + cc] = v1;
        }
    }
}

// ---------------- GEMM2 (split-K=2): out += gate * (g_h1h @ w2h + b2) -------
// blockIdx.y encodes (m-tile, k-half): m = y>>1, kh = y&1. Bias added by kh==0.
__global__ __launch_bounds__(256, 2)
void gemm2_tc(const float* __restrict__ b2, float* __restrict__ out) {
    extern __shared__ char smem[];
    const uint32_t sb = smem_u32(smem);
    const int tid = threadIdx.x;
    const int e = blockIdx.z, n0 = blockIdx.x * BN;
    const int m0 = (blockIdx.y >> 1) * BM;
    const int kh = blockIdx.y & 1;
    const int KH = DFF / 2;

    const __half* aG = g_h1h + (size_t)(e * NK + m0) * DFF + kh * KH;
    const __half* bG = g_w2h + (size_t)e * DFF * HID + (size_t)kh * KH * HID + n0;
    float acc[4][4][4];
    gemm_mainloop(acc, sb, tid, aG, DFF, bG, HID, KH);

    const int wid = tid >> 5, lane = tid & 31;
    const int wm = wid & 1, wn = wid >> 1;
    const int g = lane >> 2, c = lane & 3;
    const float bsel = (kh == 0) ? 1.f : 0.f;
#pragma unroll
    for (int mt = 0; mt < 4; mt++) {
        const int r0 = m0 + wm * 64 + mt * 16 + g;
        const int tok0 = g_idx[e * NK + r0];
        const int tok1 = g_idx[e * NK + r0 + 8];
        const float g0 = g_gate[e * NK + r0];
        const float g1 = g_gate[e * NK + r0 + 8];
#pragma unroll
        for (int nt = 0; nt < 4; nt++) {
            const int cc = n0 + wn * 32 + nt * 8 + 2 * c;
            const float bx = b2[(size_t)e * HID + cc] * bsel;
            const float by = b2[(size_t)e * HID + cc + 1] * bsel;
            atomicAdd(out + (size_t)tok0 * HID + cc,     (acc[mt][nt][0] + bx) * g0);
            atomicAdd(out + (size_t)tok0 * HID + cc + 1, (acc[mt][nt][1] + by) * g0);
            atomicAdd(out + (size_t)tok1 * HID + cc,     (acc[mt][nt][2] + bx) * g1);
            atomicAdd(out + (size_t)tok1 * HID + cc + 1, (acc[mt][nt][3] + by) * g1);
        }
    }
}

// ---------------- launch ----------------------------------------------------
extern "C" void kernel_launch(void* const* d_in, const int* in_sizes, int n_in,
                              void* d_out, int out_size) {
    const float* x  = (const float*)d_in[0];
    const float* rw = (const float*)d_in[1];
    const float* rb = (const float*)d_in[2];
    const float* w1 = (const float*)d_in[3];
    const float* b1 = (const float*)d_in[4];
    const float* w2 = (const float*)d_in[5];
    const float* b2 = (const float*)d_in[6];
    float* out = (float*)d_out;

    cudaFuncSetAttribute(gemm1_tc, cudaFuncAttributeMaxDynamicSharedMemorySize, SMEM_SZ);
    cudaFuncSetAttribute(gemm2_tc, cudaFuncAttributeMaxDynamicSharedMemorySize, SMEM_SZ);

    router_cvt<<<BSQ / 8 + RCV_CVT + RCV_ZERO, 256>>>(x, rw, rb, w1, w2, out);
    topk_cvt<<<NE + 504, 1024>>>(w1, w2);
    gather_cvt<<<NE * NK + 2048, 256>>>(x, w1, w2);
    gemm1_tc<<<dim3(DFF / BN, NK / BM, NE), 256, SMEM_SZ>>>(b1);
    gemm2_tc<<<dim3(HID / BN, (NK / BM) * 2, NE), 256, SMEM_SZ>>>(b2, out);
}

// round 16
// speedup vs baseline: 1.0513x; 1.0207x over previous
#include <cuda_runtime.h>
#include <cuda_fp16.h>
#include <cstdint>
#include <math.h>

#define BSQ 8192   // B*S tokens
#define HID 1024
#define DFF 4096
#define NE  8
#define NK  2048

// GEMM tiling: CTA 128x128x64, 8 warps of 64x32, fp16 m16n8k16, 2 CTAs/SM (R10 config)
#define BM 128
#define BN 128
#define BK 64
#define NSTAGE 3
#define RSA 72                           // A row stride (halves): 144B rows, ldsm conflict-free
#define RSB 136                          // B row stride (halves): 272B rows, conflict-free
#define A_BYTES_ST (BM * RSA * 2)        // 18432
#define B_BYTES_ST (BK * RSB * 2)        // 17408
#define STAGE_BYTES (A_BYTES_ST + B_BYTES_ST)   // 35840
#define SMEM_SZ (NSTAGE * STAGE_BYTES)          // 107520 -> 2 CTAs/SM

#define N4 ((size_t)NE * HID * DFF / 4)  // float4 count per weight tensor
#define OUT4 ((size_t)BSQ * HID / 4)     // float4 count of output
#define C1 ((N4 * 8) / 25)               // cvt chunk boundaries (0.32 / 0.72)
#define C2 ((N4 * 18) / 25)

// ---------------- scratch -------------------------------------------------
__device__ float g_scores[BSQ * NE];
__device__ int   g_idx[NE * NK];
__device__ float g_gate[NE * NK];
__device__ __align__(256) __half g_h1h[(size_t)NE * NK * DFF];   // 128MB h1 (fp16)
__device__ __align__(256) __half g_Ah[(size_t)NE * NK * HID];    // 32MB gathered tokens
__device__ __align__(256) __half g_w1h[(size_t)NE * HID * DFF];  // 64MB w1 fp16
__device__ __align__(256) __half g_w2h[(size_t)NE * DFF * HID];  // 64MB w2 fp16

// ---------------- helpers ---------------------------------------------------
__device__ __forceinline__ uint32_t smem_u32(const void* p) {
    uint32_t a;
    asm("{ .reg .u64 t; cvta.to.shared.u64 t, %1; cvt.u32.u64 %0, t; }" : "=r"(a) : "l"(p));
    return a;
}
__device__ __forceinline__ void cp16(uint32_t dst, const void* src) {
    asm volatile("cp.async.cg.shared.global [%0], [%1], 16;" :: "r"(dst), "l"(src));
}
__device__ __forceinline__ void cp_commit() {
    asm volatile("cp.async.commit_group;" ::: "memory");
}
__device__ __forceinline__ void cp_wait1() {
    asm volatile("cp.async.wait_group 1;" ::: "memory");
}
__device__ __forceinline__ void ldsm4(uint32_t* r, uint32_t addr) {
    asm volatile("ldmatrix.sync.aligned.m8n8.x4.shared.b16 {%0,%1,%2,%3}, [%4];"
                 : "=r"(r[0]), "=r"(r[1]), "=r"(r[2]), "=r"(r[3]) : "r"(addr));
}
__device__ __forceinline__ void ldsm4t(uint32_t* r, uint32_t addr) {
    asm volatile("ldmatrix.sync.aligned.m8n8.x4.trans.shared.b16 {%0,%1,%2,%3}, [%4];"
                 : "=r"(r[0]), "=r"(r[1]), "=r"(r[2]), "=r"(r[3]) : "r"(addr));
}
__device__ __forceinline__ void mma_f16(float* d, const uint32_t* a, const uint32_t* b) {
    asm volatile("mma.sync.aligned.m16n8k16.row.col.f32.f16.f16.f32 "
                 "{%0,%1,%2,%3}, {%4,%5,%6,%7}, {%8,%9}, {%0,%1,%2,%3};"
                 : "+f"(d[0]), "+f"(d[1]), "+f"(d[2]), "+f"(d[3])
                 : "r"(a[0]), "r"(a[1]), "r"(a[2]), "r"(a[3]), "r"(b[0]), "r"(b[1]));
}

// grid-stride fp32->fp16 weight conversion (both tensors) over float4 [lo, hi)
// unrolled x2: 4 independent 16B loads in flight per iteration (MLP >= 4)
__device__ __forceinline__ void cvt_chunk(const float* __restrict__ w1,
                                          const float* __restrict__ w2,
                                          size_t lo, size_t hi,
                                          int cb, int ncb) {
    const size_t stride = (size_t)ncb * blockDim.x;
    size_t i = lo + (size_t)cb * blockDim.x + threadIdx.x;
    for (; i + stride < hi; i += 2 * stride) {
        const size_t j = i + stride;
        float4 a0 = ((const float4*)w1)[i];
        float4 b0 = ((const float4*)w2)[i];
        float4 a1 = ((const float4*)w1)[j];
        float4 b1 = ((const float4*)w2)[j];
        ((__half2*)g_w1h)[2 * i]     = __floats2half2_rn(a0.x, a0.y);
        ((__half2*)g_w1h)[2 * i + 1] = __floats2half2_rn(a0.z, a0.w);
        ((__half2*)g_w2h)[2 * i]     = __floats2half2_rn(b0.x, b0.y);
        ((__half2*)g_w2h)[2 * i + 1] = __floats2half2_rn(b0.z, b0.w);
        ((__half2*)g_w1h)[2 * j]     = __floats2half2_rn(a1.x, a1.y);
        ((__half2*)g_w1h)[2 * j + 1] = __floats2half2_rn(a1.z, a1.w);
        ((__half2*)g_w2h)[2 * j]     = __floats2half2_rn(b1.x, b1.y);
        ((__half2*)g_w2h)[2 * j + 1] = __floats2half2_rn(b1.z, b1.w);
    }
    if (i < hi) {
        float4 a0 = ((const float4*)w1)[i];
        float4 b0 = ((const float4*)w2)[i];
        ((__half2*)g_w1h)[2 * i]     = __floats2half2_rn(a0.x, a0.y);
        ((__half2*)g_w1h)[2 * i + 1] = __floats2half2_rn(a0.z, a0.w);
        ((__half2*)g_w2h)[2 * i]     = __floats2half2_rn(b0.x, b0.y);
        ((__half2*)g_w2h)[2 * i + 1] = __floats2half2_rn(b0.z, b0.w);
    }
}

// ---------------- phase 1: router + cvt chunk 1 + out zeroing ---------------
#define RCV_CVT 1536
#define RCV_ZERO 512
__global__ void router_cvt(const float* __restrict__ x,
                           const float* __restrict__ rw,
                           const float* __restrict__ rb,
                           const float* __restrict__ w1,
                           const float* __restrict__ w2,
                           float* __restrict__ out) {
    __shared__ float srw[NE][HID];
    __shared__ float srb[NE];
    if (blockIdx.x >= BSQ / 8 + RCV_CVT) {             // zero the output
        const int cb = blockIdx.x - BSQ / 8 - RCV_CVT;
        const size_t stride = (size_t)RCV_ZERO * blockDim.x;
        const float4 z = make_float4(0.f, 0.f, 0.f, 0.f);
        for (size_t i = (size_t)cb * blockDim.x + threadIdx.x; i < OUT4; i += stride)
            ((float4*)out)[i] = z;
        return;
    }
    if (blockIdx.x >= BSQ / 8) {
        cvt_chunk(w1, w2, 0, C1, blockIdx.x - BSQ / 8, RCV_CVT);
        return;
    }
    const int tid = threadIdx.x;
    for (int i = tid; i < HID * NE; i += 256) {
        int h = i >> 3, e = i & 7;
        srw[e][h] = rw[i];
    }
    if (tid < NE) srb[tid] = rb[tid];
    __syncthreads();

    const int w = tid >> 5, lane = tid & 31;
    const int t = blockIdx.x * 8 + w;
    const float* xr = x + (size_t)t * HID;
    float acc[NE];
#pragma unroll
    for (int e = 0; e < NE; e++) acc[e] = 0.f;
    for (int h = lane; h < HID; h += 32) {
        float xv = xr[h];
#pragma unroll
        for (int e = 0; e < NE; e++) acc[e] = fmaf(xv, srw[e][h], acc[e]);
    }
#pragma unroll
    for (int e = 0; e < NE; e++) {
#pragma unroll
        for (int off = 16; off > 0; off >>= 1)
            acc[e] += __shfl_down_sync(0xffffffffu, acc[e], off);
    }
    if (lane == 0) {
        float m = -1e30f;
#pragma unroll
        for (int e = 0; e < NE; e++) { acc[e] += srb[e]; m = fmaxf(m, acc[e]); }
        float s = 0.f;
#pragma unroll
        for (int e = 0; e < NE; e++) { acc[e] = expf(acc[e] - m); s += acc[e]; }
        float inv = 1.f / s;
#pragma unroll
        for (int e = 0; e < NE; e++) g_scores[(size_t)t * NE + e] = acc[e] * inv;
    }
}

// ---------------- phase 2: top-K + cvt chunk 2 ------------------------------
__global__ void topk_cvt(const float* __restrict__ w1, const float* __restrict__ w2) {
    __shared__ int sg[1024];
    __shared__ int se[1024];
    __shared__ int red;
    if (blockIdx.x >= NE) {
        cvt_chunk(w1, w2, C1, C2, blockIdx.x - NE, gridDim.x - NE);
        return;
    }
    const int e = blockIdx.x;
    const int tid = threadIdx.x;

    unsigned v[8];
#pragma unroll
    for (int j = 0; j < 8; j++) {
        int i = tid * 8 + j;
        v[j] = __float_as_uint(g_scores[(size_t)i * NE + e]);
    }
    if (tid == 0) red = 0;
    __syncthreads();

    // softmax scores in [0,2) -> bits 31,30 always 0; radix from bit 29
    unsigned prefix = 0;
    int kr = NK;
    for (int bit = 29; bit >= 0; --bit) {
        unsigned want = (prefix >> bit) | 1u;
        int local = 0;
#pragma unroll
        for (int j = 0; j < 8; j++) local += ((v[j] >> bit) == want);
#pragma unroll
        for (int off = 16; off > 0; off >>= 1)
            local += __shfl_down_sync(0xffffffffu, local, off);
        if ((tid & 31) == 0) atomicAdd(&red, local);
        __syncthreads();
        int cnt = red;
        __syncthreads();
        if (tid == 0) red = 0;
        if (cnt >= kr) prefix |= (1u << bit); else kr -= cnt;
        __syncthreads();
    }
    const unsigned thr = prefix;

    int cg = 0, ce = 0;
#pragma unroll
    for (int j = 0; j < 8; j++) { cg += (v[j] > thr); ce += (v[j] == thr); }
    sg[tid] = cg; se[tid] = ce;
    __syncthreads();
    for (int d = 1; d < 1024; d <<= 1) {
        int a = (tid >= d) ? sg[tid - d] : 0;
        int b = (tid >= d) ? se[tid - d] : 0;
        __syncthreads();
        sg[tid] += a; se[tid] += b;
        __syncthreads();
    }
    const int C = sg[1023];
    int pg = sg[tid] - cg;
    int pe = se[tid] - ce;
    const int need = NK - C;
#pragma unroll
    for (int j = 0; j < 8; j++) {
        int tok = tid * 8 + j;
        if (v[j] > thr) {
            g_idx[e * NK + pg] = tok;
            g_gate[e * NK + pg] = __uint_as_float(v[j]);
            pg++;
        } else if (v[j] == thr) {
            if (pe < need) {
                int pos = C + pe;
                g_idx[e * NK + pos] = tok;
                g_gate[e * NK + pos] = __uint_as_float(v[j]);
            }
            pe++;
        }
    }
}

// ---------------- phase 3: gather + cvt chunk 3 -----------------------------
__global__ void gather_cvt(const float* __restrict__ x,
                           const float* __restrict__ w1,
                           const float* __restrict__ w2) {
    if (blockIdx.x >= NE * NK) {
        cvt_chunk(w1, w2, C2, N4, blockIdx.x - NE * NK, gridDim.x - NE * NK);
        return;
    }
    const int row = blockIdx.x;
    const int tok = g_idx[row];
    const float4* s = (const float4*)(x + (size_t)tok * HID);
    float4 v = s[threadIdx.x];
    __half2* d = (__half2*)(g_Ah + (size_t)row * HID) + threadIdx.x * 2;
    d[0] = __floats2half2_rn(v.x, v.y);
    d[1] = __floats2half2_rn(v.z, v.w);
}

// ---------------- fp16 mma mainloop (R10 config: 8 warps, 64x32 tiles) ------
__device__ __forceinline__ void load_stage(uint32_t sb, int buf, int tid,
                                           const __half* aG, int Ast,
                                           const __half* bG, int Nld, int k0) {
    const uint32_t baseA = sb + buf * STAGE_BYTES;
    const uint32_t baseB = baseA + A_BYTES_ST;
#pragma unroll
    for (int i = 0; i < 4; i++) {                       // A: 1024 cp16 (128 rows x 128B)
        int id = tid + (i << 8);
        int r = id >> 3, c = id & 7;
        cp16(baseA + r * (RSA * 2) + c * 16, aG + (size_t)r * Ast + k0 + c * 8);
    }
#pragma unroll
    for (int i = 0; i < 4; i++) {                       // B: 1024 cp16 (64 rows x 256B)
        int id = tid + (i << 8);
        int kr = id >> 4, nc = id & 15;
        cp16(baseB + kr * (RSB * 2) + nc * 16, bG + (size_t)(k0 + kr) * Nld + nc * 8);
    }
}

__device__ __forceinline__ void gemm_mainloop(float acc[4][4][4], uint32_t sb, int tid,
                                              const __half* aG, int Ast,
                                              const __half* bG, int Nld, int Kd) {
    const int wid = tid >> 5, lane = tid & 31;
    const int wm = wid & 1, wn = wid >> 1;              // 2 x 4 warp grid, 64x32 tiles
    const int lane15 = lane & 15, laneh = lane >> 4;
    const int KT = Kd / BK;
    const uint32_t aLane = (uint32_t)(wm * 64 + lane15) * (RSA * 2) + laneh * 16;
    const uint32_t bLane = (uint32_t)lane15 * (RSB * 2) + wn * 64 + laneh * 16;

#pragma unroll
    for (int mt = 0; mt < 4; mt++)
#pragma unroll
        for (int nt = 0; nt < 4; nt++)
#pragma unroll
            for (int q = 0; q < 4; q++) acc[mt][nt][q] = 0.f;

    for (int s = 0; s < NSTAGE - 1; s++) {
        load_stage(sb, s, tid, aG, Ast, bG, Nld, s * BK);
        cp_commit();
    }

    for (int k = 0; k < KT; k++) {
        const int buf = k % NSTAGE;
        cp_wait1();
        __syncthreads();   // single barrier per iter: also fences prior-iter reads
                           // before this iter's loads overwrite buf (k+2)%3

        const uint32_t bufA = sb + buf * STAGE_BYTES + aLane;
        const uint32_t bufB = sb + buf * STAGE_BYTES + A_BYTES_ST + bLane;
#pragma unroll
        for (int kk = 0; kk < 4; kk++) {
            uint32_t aF[4][4], bF[2][4];
#pragma unroll
            for (int mt = 0; mt < 4; mt++)
                ldsm4(aF[mt], bufA + mt * (16 * RSA * 2) + kk * 32);
#pragma unroll
            for (int np = 0; np < 2; np++)
                ldsm4t(bF[np], bufB + kk * (16 * RSB * 2) + np * 32);
#pragma unroll
            for (int mt = 0; mt < 4; mt++)
#pragma unroll
                for (int np = 0; np < 2; np++) {
                    mma_f16(acc[mt][2 * np],     aF[mt], &bF[np][0]);
                    mma_f16(acc[mt][2 * np + 1], aF[mt], &bF[np][2]);
                }
        }

        const int pf = k + NSTAGE - 1;
        if (pf < KT) load_stage(sb, pf % NSTAGE, tid, aG, Ast, bG, Nld, pf * BK);
        cp_commit();   // empty group when no prefetch keeps wait_group invariant
    }
}

// ---------------- GEMM1: g_h1h = half(relu(g_Ah @ w1h + b1)) ----------------
__global__ __launch_bounds__(256, 2)
void gemm1_tc(const float* __restrict__ b1) {
    extern __shared__ char smem[];
    const uint32_t sb = smem_u32(smem);
    const int tid = threadIdx.x;
    const int e = blockIdx.z, n0 = blockIdx.x * BN, m0 = blockIdx.y * BM;

    const __half* aG = g_Ah + (size_t)(e * NK + m0) * HID;
    const __half* bG = g_w1h + (size_t)e * HID * DFF + n0;
    float acc[4][4][4];
    gemm_mainloop(acc, sb, tid, aG, HID, bG, DFF, HID);

    const int wid = tid >> 5, lane = tid & 31;
    const int wm = wid & 1, wn = wid >> 1;
    const int g = lane >> 2, c = lane & 3;
#pragma unroll
    for (int mt = 0; mt < 4; mt++) {
        const int r0 = m0 + wm * 64 + mt * 16 + g;
#pragma unroll
        for (int nt = 0; nt < 4; nt++) {
            const int cc = n0 + wn * 32 + nt * 8 + 2 * c;
            const float bx = b1[(size_t)e * DFF + cc];
            const float by = b1[(size_t)e * DFF + cc + 1];
            __half2 v0 = __floats2half2_rn(fmaxf(acc[mt][nt][0] + bx, 0.f),
                                           fmaxf(acc[mt][nt][1] + by, 0.f));
            __half2 v1 = __floats2half2_rn(fmaxf(acc[mt][nt][2] + bx, 0.f),
                                           fmaxf(acc[mt][nt][3] + by, 0.f));
            *(__half2*)&g_h1h[(size_t)(e * NK + r0) * DFF + cc] = v0;
            *(__half2*)&g_h1h[(size_t)(e * NK + r0 + 8) * DFF + cc] = v1;
        }
    }
}

// ---------------- GEMM2 (R10 form): out += gate * (g_h1h @ w2h + b2) --------
__global__ __launch_bounds__(256, 2)
void gemm2_tc(const float* __restrict__ b2, float* __restrict__ out) {
    extern __shared__ char smem[];
    const uint32_t sb = smem_u32(smem);
    const int tid = threadIdx.x;
    const int e = blockIdx.z, n0 = blockIdx.x * BN, m0 = blockIdx.y * BM;

    const __half* aG = g_h1h + (size_t)(e * NK + m0) * DFF;
    const __half* bG = g_w2h + (size_t)e * DFF * HID + n0;
    float acc[4][4][4];
    gemm_mainloop(acc, sb, tid, aG, DFF, bG, HID, DFF);

    const int wid = tid >> 5, lane = tid & 31;
    const int wm = wid & 1, wn = wid >> 1;
    const int g = lane >> 2, c = lane & 3;
#pragma unroll
    for (int mt = 0; mt < 4; mt++) {
        const int r0 = m0 + wm * 64 + mt * 16 + g;
        const int tok0 = g_idx[e * NK + r0];
        const int tok1 = g_idx[e * NK + r0 + 8];
        const float g0 = g_gate[e * NK + r0];
        const float g1 = g_gate[e * NK + r0 + 8];
#pragma unroll
        for (int nt = 0; nt < 4; nt++) {
            const int cc = n0 + wn * 32 + nt * 8 + 2 * c;
            const float bx = b2[(size_t)e * HID + cc];
            const float by = b2[(size_t)e * HID + cc + 1];
            atomicAdd(out + (size_t)tok0 * HID + cc,     (acc[mt][nt][0] + bx) * g0);
            atomicAdd(out + (size_t)tok0 * HID + cc + 1, (acc[mt][nt][1] + by) * g0);
            atomicAdd(out + (size_t)tok1 * HID + cc,     (acc[mt][nt][2] + bx) * g1);
            atomicAdd(out + (size_t)tok1 * HID + cc + 1, (acc[mt][nt][3] + by) * g1);
        }
    }
}

// ---------------- launch ----------------------------------------------------
extern "C" void kernel_launch(void* const* d_in, const int* in_sizes, int n_in,
                              void* d_out, int out_size) {
    const float* x  = (const float*)d_in[0];
    const float* rw = (const float*)d_in[1];
    const float* rb = (const float*)d_in[2];
    const float* w1 = (const float*)d_in[3];
    const float* b1 = (const float*)d_in[4];
    const float* w2 = (const float*)d_in[5];
    const float* b2 = (const float*)d_in[6];
    float* out = (float*)d_out;

    cudaFuncSetAttribute(gemm1_tc, cudaFuncAttributeMaxDynamicSharedMemorySize, SMEM_SZ);
    cudaFuncSetAttribute(gemm2_tc, cudaFuncAttributeMaxDynamicSharedMemorySize, SMEM_SZ);

    router_cvt<<<BSQ / 8 + RCV_CVT + RCV_ZERO, 256>>>(x, rw, rb, w1, w2, out);
    topk_cvt<<<NE + 504, 1024>>>(w1, w2);
    gather_cvt<<<NE * NK + 2048, 256>>>(x, w1, w2);
    gemm1_tc<<<dim3(DFF / BN, NK / BM, NE), 256, SMEM_SZ>>>(b1);
    gemm2_tc<<<dim3(HID / BN, NK / BM, NE), 256, SMEM_SZ>>>(b2, out);
}